// round 2
// baseline (speedup 1.0000x reference)
#include <cuda_runtime.h>
#include <cstdint>

// Problem constants
#define B    16
#define DI   24        // input spatial
#define CI   64
#define DO   26        // output spatial (24 + 2)
#define CO   128
#define NGRP 8
#define CPG  16        // channels per group
#define EPS  1e-5f

#define TILE 4         // output tile per dim
#define NT   7         // ceil(26/4)
#define RS   6         // halo region per dim (TILE + 2)

#define XS_FLOATS (RS*RS*RS*CI)   // 13824
#define WS_FLOATS (CI*CO)         // 8192
#define SMEM_FLOATS (XS_FLOATS + WS_FLOATS + 16)
#define SMEM_BYTES (SMEM_FLOATS * 4)   // 88,128 B

#define Y_ELEMS ((size_t)B*DO*DO*DO*CO)   // 35,995,648

// Scratch: conv+relu output, and per-(b,group) sum / sumsq accumulators.
__device__ float g_y[Y_ELEMS];
__device__ float g_sum[B*NGRP];
__device__ float g_ssq[B*NGRP];

__global__ void zero_stats_kernel() {
    int t = threadIdx.x;
    if (t < B*NGRP) { g_sum[t] = 0.f; g_ssq[t] = 0.f; }
}

// Each CTA: one 4x4x4 output tile x all 128 c_out, for one batch.
// threadIdx: cg = t&31 -> c_out quad (co = cg*4); rp = t>>5 -> 2 of 16 (dd,hh) rows.
__global__ void __launch_bounds__(256, 2)
conv_relu_kernel(const float* __restrict__ x, const float* __restrict__ w)
{
    extern __shared__ float smem[];
    float* xs  = smem;                       // [6][6][6][64], ci innermost
    float* ws  = smem + XS_FLOATS;           // [64][128]
    float* red = smem + XS_FLOATS + WS_FLOATS; // [16]: 8 sums, 8 sumsqs

    const int b  = blockIdx.y;
    const int bx = blockIdx.x;
    const int tz = bx / (NT*NT);
    const int ty = (bx / NT) % NT;
    const int tx = bx % NT;
    const int od0 = tz*TILE, oh0 = ty*TILE, ow0 = tx*TILE;
    const int i0d = od0 - 2, i0h = oh0 - 2, i0w = ow0 - 2;
    const int t  = threadIdx.x;
    const int cg = t & 31;     // c_out quad index
    const int rp = t >> 5;     // row-pair index 0..7

    if (t < 16) red[t] = 0.f;

    // ---- stage input halo tile (zero-padded) ----
    const float* xb = x + (size_t)b * (DI*DI*DI*CI);
    for (int idx = t; idx < RS*RS*RS*(CI/4); idx += 256) {
        int ci4 = idx & 15;
        int p   = idx >> 4;                  // 0..215
        int wx  = p % RS;
        int hy  = (p / RS) % RS;
        int dz  = p / (RS*RS);
        int id = i0d + dz, ih = i0h + hy, iw = i0w + wx;
        float4 v = make_float4(0.f, 0.f, 0.f, 0.f);
        if ((unsigned)id < DI && (unsigned)ih < DI && (unsigned)iw < DI)
            v = *(const float4*)(xb + ((size_t)((id*DI + ih)*DI + iw))*CI + ci4*4);
        *(float4*)(xs + p*CI + ci4*4) = v;
    }

    float acc[2][4][4];
    #pragma unroll
    for (int a = 0; a < 2; ++a)
        #pragma unroll
        for (int q = 0; q < 4; ++q)
            #pragma unroll
            for (int c = 0; c < 4; ++c) acc[a][q][c] = 0.f;

    const int r0 = 2*rp;
    const int dd0 = r0 >> 2,      hh0 = r0 & 3;
    const int dd1 = (r0+1) >> 2,  hh1 = (r0+1) & 3;

    for (int tap = 0; tap < 27; ++tap) {
        const int kd = tap / 9, kh = (tap / 3) % 3, kw = tap % 3;
        __syncthreads();   // xs ready (tap 0) / ws no longer in use (tap > 0)
        // stage flipped-tap weight slice [64][128] (contiguous in global)
        const float* wt = w + (size_t)((2-kd)*9 + (2-kh)*3 + (2-kw)) * (CI*CO);
        for (int idx = t; idx < (CI*CO)/4; idx += 256)
            *(float4*)(ws + idx*4) = *(const float4*)(wt + idx*4);
        __syncthreads();

        const int dzA = dd0 + kd, hyA = hh0 + kh;
        const int dzB = dd1 + kd, hyB = hh1 + kh;
        const float* xrowA = xs + ((dzA*RS + hyA)*RS + kw)*CI;
        const float* xrowB = xs + ((dzB*RS + hyB)*RS + kw)*CI;

        #pragma unroll 2
        for (int ci = 0; ci < CI; ci += 4) {
            float4 w0 = *(const float4*)(ws + (ci+0)*CO + cg*4);
            float4 w1 = *(const float4*)(ws + (ci+1)*CO + cg*4);
            float4 w2 = *(const float4*)(ws + (ci+2)*CO + cg*4);
            float4 w3 = *(const float4*)(ws + (ci+3)*CO + cg*4);
            #pragma unroll
            for (int q = 0; q < 4; ++q) {
                float4 xv = *(const float4*)(xrowA + q*CI + ci);
                acc[0][q][0] += xv.x*w0.x + xv.y*w1.x + xv.z*w2.x + xv.w*w3.x;
                acc[0][q][1] += xv.x*w0.y + xv.y*w1.y + xv.z*w2.y + xv.w*w3.y;
                acc[0][q][2] += xv.x*w0.z + xv.y*w1.z + xv.z*w2.z + xv.w*w3.z;
                acc[0][q][3] += xv.x*w0.w + xv.y*w1.w + xv.z*w2.w + xv.w*w3.w;
            }
            #pragma unroll
            for (int q = 0; q < 4; ++q) {
                float4 xv = *(const float4*)(xrowB + q*CI + ci);
                acc[1][q][0] += xv.x*w0.x + xv.y*w1.x + xv.z*w2.x + xv.w*w3.x;
                acc[1][q][1] += xv.x*w0.y + xv.y*w1.y + xv.z*w2.y + xv.w*w3.y;
                acc[1][q][2] += xv.x*w0.z + xv.y*w1.z + xv.z*w2.z + xv.w*w3.z;
                acc[1][q][3] += xv.x*w0.w + xv.y*w1.w + xv.z*w2.w + xv.w*w3.w;
            }
        }
    }

    // ---- ReLU, store, and GroupNorm partial stats ----
    float s = 0.f, ss = 0.f;
    #pragma unroll
    for (int rr = 0; rr < 2; ++rr) {
        const int r  = 2*rp + rr;
        const int od = od0 + (r >> 2);
        const int oh = oh0 + (r & 3);
        if (od < DO && oh < DO) {
            #pragma unroll
            for (int q = 0; q < 4; ++q) {
                const int ow = ow0 + q;
                if (ow < DO) {
                    float4 v;
                    v.x = fmaxf(acc[rr][q][0], 0.f);
                    v.y = fmaxf(acc[rr][q][1], 0.f);
                    v.z = fmaxf(acc[rr][q][2], 0.f);
                    v.w = fmaxf(acc[rr][q][3], 0.f);
                    *(float4*)(g_y + ((((size_t)b*DO + od)*DO + oh)*DO + ow)*CO + cg*4) = v;
                    s  += v.x + v.y + v.z + v.w;
                    ss += v.x*v.x + v.y*v.y + v.z*v.z + v.w*v.w;
                }
            }
        }
    }

    // lanes 4k..4k+3 share group g = cg>>2
    s  += __shfl_down_sync(0xffffffffu, s, 2);
    s  += __shfl_down_sync(0xffffffffu, s, 1);
    ss += __shfl_down_sync(0xffffffffu, ss, 2);
    ss += __shfl_down_sync(0xffffffffu, ss, 1);
    if ((cg & 3) == 0) {
        int g = cg >> 2;
        atomicAdd(&red[g],     s);
        atomicAdd(&red[8 + g], ss);
    }
    __syncthreads();
    if (t < NGRP)             atomicAdd(&g_sum[b*NGRP + t],       red[t]);
    else if (t < 2*NGRP)      atomicAdd(&g_ssq[b*NGRP + (t-8)],   red[t]);
}

__global__ void norm_kernel(const float* __restrict__ gn_scale,
                            const float* __restrict__ gn_bias,
                            float* __restrict__ out)
{
    const int i = blockIdx.x * blockDim.x + threadIdx.x;   // float4 index
    const size_t e = (size_t)i * 4;
    if (e >= Y_ELEMS) return;
    const int c    = (int)(e & (CO-1));
    const int rest = (int)(e >> 7);          // (b,d,h,w) linear
    const int b    = rest / (DO*DO*DO);
    const int g    = c >> 4;
    const float cnt = (float)(DO*DO*DO*CPG);
    const float m   = g_sum[b*NGRP + g] / cnt;
    const float var = g_ssq[b*NGRP + g] / cnt - m*m;
    const float inv = rsqrtf(var + EPS);
    const float4 v  = *(const float4*)(g_y + e);
    const float4 sc = *(const float4*)(gn_scale + c);
    const float4 bi = *(const float4*)(gn_bias + c);
    float4 o;
    o.x = (v.x - m) * inv * sc.x + bi.x;
    o.y = (v.y - m) * inv * sc.y + bi.y;
    o.z = (v.z - m) * inv * sc.z + bi.z;
    o.w = (v.w - m) * inv * sc.w + bi.w;
    *(float4*)(out + e) = o;
}

extern "C" void kernel_launch(void* const* d_in, const int* in_sizes, int n_in,
                              void* d_out, int out_size)
{
    const float* x  = (const float*)d_in[0];
    const float* w  = (const float*)d_in[1];
    const float* sc = (const float*)d_in[2];
    const float* bi = (const float*)d_in[3];
    float* out = (float*)d_out;

    cudaFuncSetAttribute(conv_relu_kernel,
                         cudaFuncAttributeMaxDynamicSharedMemorySize, SMEM_BYTES);

    zero_stats_kernel<<<1, 128>>>();
    conv_relu_kernel<<<dim3(NT*NT*NT, B), 256, SMEM_BYTES>>>(x, w);

    const int total4 = (int)(Y_ELEMS / 4);             // 8,998,912
    const int blocks = (total4 + 255) / 256;           // 35,152
    norm_kernel<<<blocks, 256>>>(sc, bi, out);
}

// round 7
// speedup vs baseline: 1.8623x; 1.8623x over previous
#include <cuda_runtime.h>
#include <cuda_bf16.h>
#include <cstdint>

// ---------------- problem constants ----------------
#define B_    16
#define DI    24
#define CI    64
#define DO    26
#define CO    128
#define NGRP  8
#define EPS   1e-5f

#define VOL   (DO*DO*DO)               // 17576
#define NPOS  (B_*VOL)                 // 281216
#define MTILE 128
#define NTILES (NPOS/MTILE)            // 2197 exactly
#define Y_ELEMS ((size_t)NPOS*CO)      // 35,995,648
#define XN    ((size_t)B_*DI*DI*DI*CI) // 14,155,776
#define WN    (27*CI*CO)               // 221,184

// padded smem row stride (bf16 elements): conflict-free for frag loads & staging
#define STR   72
#define TILE_E (128*STR)               // 9216 bf16 per tile
#define SMEM_E (4*TILE_E)              // AH, AL, BH, BL
#define DYN_SMEM (SMEM_E*2)            // 73728 bytes

// ---------------- device scratch ----------------
__device__ float g_y[Y_ELEMS];
__device__ float g_sum[B_*NGRP];
__device__ float g_ssq[B_*NGRP];
__device__ __nv_bfloat16 g_xh[XN];
__device__ __nv_bfloat16 g_xl[XN];
__device__ __nv_bfloat16 g_wh[WN];   // [tap][co][ci], tap pre-flipped
__device__ __nv_bfloat16 g_wl[WN];

// ---------------- mma.sync m16n8k16 bf16 (plain sm_103-legal HMMA) ----------
__device__ __forceinline__ void mma16816(float* d, const uint32_t* a, const uint32_t* b) {
    asm volatile(
        "mma.sync.aligned.m16n8k16.row.col.f32.bf16.bf16.f32 "
        "{%0,%1,%2,%3}, {%4,%5,%6,%7}, {%8,%9}, {%0,%1,%2,%3};"
        : "+f"(d[0]), "+f"(d[1]), "+f"(d[2]), "+f"(d[3])
        : "r"(a[0]), "r"(a[1]), "r"(a[2]), "r"(a[3]), "r"(b[0]), "r"(b[1]));
}

// ---------------- prepass kernels ----------------
__global__ void prep_x(const float* __restrict__ x) {
    size_t i = (size_t)blockIdx.x * 256 + threadIdx.x;   // float4 index
    if (i * 4 >= XN) return;
    float4 v = __ldg((const float4*)x + i);
    __nv_bfloat16 h0 = __float2bfloat16(v.x), h1 = __float2bfloat16(v.y);
    __nv_bfloat16 h2 = __float2bfloat16(v.z), h3 = __float2bfloat16(v.w);
    __nv_bfloat16 l0 = __float2bfloat16(v.x - __bfloat162float(h0));
    __nv_bfloat16 l1 = __float2bfloat16(v.y - __bfloat162float(h1));
    __nv_bfloat16 l2 = __float2bfloat16(v.z - __bfloat162float(h2));
    __nv_bfloat16 l3 = __float2bfloat16(v.w - __bfloat162float(h3));
    ((__nv_bfloat162*)g_xh)[i*2]   = __nv_bfloat162(h0, h1);
    ((__nv_bfloat162*)g_xh)[i*2+1] = __nv_bfloat162(h2, h3);
    ((__nv_bfloat162*)g_xl)[i*2]   = __nv_bfloat162(l0, l1);
    ((__nv_bfloat162*)g_xl)[i*2+1] = __nv_bfloat162(l2, l3);
}

__global__ void prep_w(const float* __restrict__ w) {
    int i = blockIdx.x * 256 + threadIdx.x;
    if (i >= WN) return;
    int ci  = i & 63;
    int co  = (i >> 6) & 127;
    int tap = i >> 13;
    int kd = tap / 9, kh = (tap / 3) % 3, kw = tap % 3;
    int ftap = (2-kd)*9 + (2-kh)*3 + (2-kw);
    float v = __ldg(w + (size_t)ftap * CI * CO + ci * CO + co);
    __nv_bfloat16 h = __float2bfloat16(v);
    g_wh[i] = h;
    g_wl[i] = __float2bfloat16(v - __bfloat162float(h));
}

__global__ void zero_stats_kernel() {
    int t = threadIdx.x;
    if (t < B_*NGRP) { g_sum[t] = 0.f; g_ssq[t] = 0.f; }
}

// ---------------- main conv kernel: mma.sync implicit GEMM -------------------
// CTA = 128 raster positions x 128 c_out, 8 warps; warp tile 32(M) x 64(N).
__global__ void __launch_bounds__(256, 2)
conv_mma_kernel()
{
    extern __shared__ __align__(16) uint16_t sm[];
    uint16_t* sAH = sm;
    uint16_t* sAL = sm + TILE_E;
    uint16_t* sBH = sm + 2*TILE_E;
    uint16_t* sBL = sm + 3*TILE_E;
    __shared__ float red[32];   // [0:16) sums [slot][g], [16:32) ssq [slot][g]

    const int tid  = threadIdx.x;
    const int lane = tid & 31;
    const int wrp  = tid >> 5;
    const int mw   = wrp & 3;       // M block: mw*32
    const int nw   = wrp >> 2;      // N block: nw*64
    const int gid  = lane >> 2;     // fragment group row/col
    const int tig  = lane & 3;

    if (tid < 32) red[tid] = 0.f;

    const int tile = blockIdx.x;
    // staging role: each thread owns (row = tid>>1, half = tid&1)
    const int srow  = tid >> 1;
    const int shalf = tid & 1;
    const int spos  = tile * MTILE + srow;
    const int sb    = spos / VOL;
    const int swv   = spos % VOL;
    const int sd = swv / (DO*DO);
    const int sh = (swv / DO) % DO;
    const int sw = swv % DO;
    const size_t sbase = (size_t)sb * (DI*DI*DI);
    uint16_t* aDstH = sAH + srow*STR + shalf*32;
    uint16_t* aDstL = sAL + srow*STR + shalf*32;
    uint16_t* bDstH = sBH + srow*STR + shalf*32;
    uint16_t* bDstL = sBL + srow*STR + shalf*32;

    float acc[2][8][4];
    #pragma unroll
    for (int m = 0; m < 2; ++m)
        #pragma unroll
        for (int n = 0; n < 8; ++n)
            #pragma unroll
            for (int k = 0; k < 4; ++k) acc[m][n][k] = 0.f;

    for (int tap = 0; tap < 27; ++tap) {
        const int kd = tap / 9, kh = (tap / 3) % 3, kw = tap % 3;

        __syncthreads();   // previous tap's compute done before overwrite

        // ---- stage A: x rows (hi+lo), zero-padded out of bounds ----
        {
            const int id = sd + kd - 2, ih = sh + kh - 2, iw = sw + kw - 2;
            const bool ok = (unsigned)id < DI && (unsigned)ih < DI && (unsigned)iw < DI;
            if (ok) {
                const size_t eoff = (sbase + (size_t)((id*DI + ih)*DI + iw)) * CI + shalf*32;
                const uint4* ph = (const uint4*)(g_xh + eoff);
                const uint4* pl = (const uint4*)(g_xl + eoff);
                #pragma unroll
                for (int j = 0; j < 4; ++j) ((uint4*)aDstH)[j] = __ldg(ph + j);
                #pragma unroll
                for (int j = 0; j < 4; ++j) ((uint4*)aDstL)[j] = __ldg(pl + j);
            } else {
                uint4 z = make_uint4(0,0,0,0);
                #pragma unroll
                for (int j = 0; j < 4; ++j) ((uint4*)aDstH)[j] = z;
                #pragma unroll
                for (int j = 0; j < 4; ++j) ((uint4*)aDstL)[j] = z;
            }
        }
        // ---- stage B: weight slice [co][ci] hi+lo ----
        {
            const size_t woff = (size_t)tap * CI * CO + srow*CI + shalf*32;
            const uint4* ph = (const uint4*)(g_wh + woff);
            const uint4* pl = (const uint4*)(g_wl + woff);
            #pragma unroll
            for (int j = 0; j < 4; ++j) ((uint4*)bDstH)[j] = __ldg(ph + j);
            #pragma unroll
            for (int j = 0; j < 4; ++j) ((uint4*)bDstL)[j] = __ldg(pl + j);
        }
        __syncthreads();

        // ---- compute: 4 K-steps x (hi*hi + lo*hi + hi*lo) ----
        #pragma unroll
        for (int ks = 0; ks < 4; ++ks) {
            const int k0 = ks * 16;
            uint32_t ah[2][4], bh[8][2];
            #pragma unroll
            for (int m = 0; m < 2; ++m) {
                const int r = mw*32 + m*16 + gid;
                const uint16_t* p = sAH + r*STR + k0 + 2*tig;
                ah[m][0] = *(const uint32_t*)(p);
                ah[m][1] = *(const uint32_t*)(p + 8*STR);
                ah[m][2] = *(const uint32_t*)(p + 8);
                ah[m][3] = *(const uint32_t*)(p + 8*STR + 8);
            }
            #pragma unroll
            for (int n = 0; n < 8; ++n) {
                const int c = nw*64 + n*8 + gid;
                const uint16_t* p = sBH + c*STR + k0 + 2*tig;
                bh[n][0] = *(const uint32_t*)(p);
                bh[n][1] = *(const uint32_t*)(p + 8);
            }
            #pragma unroll
            for (int m = 0; m < 2; ++m)
                #pragma unroll
                for (int n = 0; n < 8; ++n)
                    mma16816(acc[m][n], ah[m], bh[n]);   // hi*hi

            uint32_t al[2][4];
            #pragma unroll
            for (int m = 0; m < 2; ++m) {
                const int r = mw*32 + m*16 + gid;
                const uint16_t* p = sAL + r*STR + k0 + 2*tig;
                al[m][0] = *(const uint32_t*)(p);
                al[m][1] = *(const uint32_t*)(p + 8*STR);
                al[m][2] = *(const uint32_t*)(p + 8);
                al[m][3] = *(const uint32_t*)(p + 8*STR + 8);
            }
            #pragma unroll
            for (int m = 0; m < 2; ++m)
                #pragma unroll
                for (int n = 0; n < 8; ++n)
                    mma16816(acc[m][n], al[m], bh[n]);   // lo*hi

            #pragma unroll
            for (int n = 0; n < 8; ++n) {               // overwrite bh with B-lo
                const int c = nw*64 + n*8 + gid;
                const uint16_t* p = sBL + c*STR + k0 + 2*tig;
                bh[n][0] = *(const uint32_t*)(p);
                bh[n][1] = *(const uint32_t*)(p + 8);
            }
            #pragma unroll
            for (int m = 0; m < 2; ++m)
                #pragma unroll
                for (int n = 0; n < 8; ++n)
                    mma16816(acc[m][n], ah[m], bh[n]);   // hi*lo
        }
    }

    // ---- epilogue: ReLU, store, GroupNorm partial stats ----
    const int b0 = (tile * MTILE) / VOL;
    #pragma unroll
    for (int m = 0; m < 2; ++m) {
        #pragma unroll
        for (int rh = 0; rh < 2; ++rh) {
            const int rr  = mw*32 + m*16 + gid + rh*8;
            const int pos = tile * MTILE + rr;
            const int slot = pos / VOL - b0;
            float* dst = g_y + (size_t)pos * CO + nw*64 + 2*tig;
            float s[4] = {0.f,0.f,0.f,0.f}, q[4] = {0.f,0.f,0.f,0.f};
            #pragma unroll
            for (int n = 0; n < 8; ++n) {
                float v0 = fmaxf(acc[m][n][rh*2 + 0], 0.f);
                float v1 = fmaxf(acc[m][n][rh*2 + 1], 0.f);
                *(float2*)(dst + n*8) = make_float2(v0, v1);
                s[n>>1] += v0 + v1;
                q[n>>1] += v0*v0 + v1*v1;
            }
            #pragma unroll
            for (int g = 0; g < 4; ++g) {
                atomicAdd(&red[slot*8 + nw*4 + g],      s[g]);
                atomicAdd(&red[16 + slot*8 + nw*4 + g], q[g]);
            }
        }
    }
    __syncthreads();

    if (tid < 32) {
        const int isq = tid >> 4;        // 0: sum, 1: ssq
        const int sl  = (tid >> 3) & 1;
        const int g   = tid & 7;
        const int bb  = b0 + sl;
        if (bb < B_) {
            float v = red[tid];
            if (!isq) atomicAdd(&g_sum[bb*NGRP + g], v);
            else      atomicAdd(&g_ssq[bb*NGRP + g], v);
        }
    }
}

// ---------------- normalize ----------------
__global__ void norm_kernel(const float* __restrict__ gn_scale,
                            const float* __restrict__ gn_bias,
                            float* __restrict__ out)
{
    const int i = blockIdx.x * blockDim.x + threadIdx.x;   // float4 index
    const size_t e = (size_t)i * 4;
    if (e >= Y_ELEMS) return;
    const int c    = (int)(e & (CO-1));
    const int rest = (int)(e >> 7);
    const int b    = rest / VOL;
    const int g    = c >> 4;
    const float cnt = (float)(VOL * (CO/NGRP));
    const float m   = g_sum[b*NGRP + g] / cnt;
    const float var = g_ssq[b*NGRP + g] / cnt - m*m;
    const float inv = rsqrtf(var + EPS);
    const float4 v  = *(const float4*)(g_y + e);
    const float4 sc = __ldg((const float4*)(gn_scale + c));
    const float4 bi = __ldg((const float4*)(gn_bias + c));
    float4 o;
    o.x = (v.x - m) * inv * sc.x + bi.x;
    o.y = (v.y - m) * inv * sc.y + bi.y;
    o.z = (v.z - m) * inv * sc.z + bi.z;
    o.w = (v.w - m) * inv * sc.w + bi.w;
    *(float4*)(out + e) = o;
}

extern "C" void kernel_launch(void* const* d_in, const int* in_sizes, int n_in,
                              void* d_out, int out_size)
{
    const float* x  = (const float*)d_in[0];
    const float* w  = (const float*)d_in[1];
    const float* sc = (const float*)d_in[2];
    const float* bi = (const float*)d_in[3];
    float* out = (float*)d_out;

    cudaFuncSetAttribute(conv_mma_kernel,
                         cudaFuncAttributeMaxDynamicSharedMemorySize, DYN_SMEM);

    prep_x<<<(unsigned)((XN/4 + 255) / 256), 256>>>(x);
    prep_w<<<(WN + 255) / 256, 256>>>(w);
    zero_stats_kernel<<<1, 128>>>();
    conv_mma_kernel<<<NTILES, 256, DYN_SMEM>>>();

    const int total4 = (int)(Y_ELEMS / 4);
    norm_kernel<<<(total4 + 255) / 256, 256>>>(sc, bi, out);
}

// round 8
// speedup vs baseline: 1.8634x; 1.0006x over previous
#include <cuda_runtime.h>
#include <cuda_bf16.h>
#include <cstdint>

// ---------------- problem constants ----------------
#define B_    16
#define DI    24
#define CI    64
#define DO    26
#define CO    128
#define NGRP  8
#define EPS   1e-5f

#define VOL   (DO*DO*DO)               // 17576
#define NPOS  (B_*VOL)                 // 281216
#define MTILE 128
#define NTILES (NPOS/MTILE)            // 2197 exactly
#define Y_ELEMS ((size_t)NPOS*CO)      // 35,995,648
#define XN    ((size_t)B_*DI*DI*DI*CI) // 14,155,776
#define WN    (27*CI*CO)               // 221,184

// padded smem row stride (bf16 elements): conflict-free for frag loads & staging
#define STR   72
#define TILE_E (128*STR)               // 9216 bf16 per tile
#define SMEM_E (4*TILE_E)              // AH, AL, BH, BL
#define DYN_SMEM (SMEM_E*2)            // 73728 bytes

// ---------------- device scratch ----------------
__device__ float g_y[Y_ELEMS];
__device__ float g_sum[B_*NGRP];
__device__ float g_ssq[B_*NGRP];
__device__ __nv_bfloat16 g_xh[XN];
__device__ __nv_bfloat16 g_xl[XN];
__device__ __nv_bfloat16 g_wh[WN];   // [tap][co][ci], tap pre-flipped
__device__ __nv_bfloat16 g_wl[WN];

// ---------------- mma.sync m16n8k16 bf16 (plain sm_103-legal HMMA) ----------
__device__ __forceinline__ void mma16816(float* d, const uint32_t* a, const uint32_t* b) {
    asm volatile(
        "mma.sync.aligned.m16n8k16.row.col.f32.bf16.bf16.f32 "
        "{%0,%1,%2,%3}, {%4,%5,%6,%7}, {%8,%9}, {%0,%1,%2,%3};"
        : "+f"(d[0]), "+f"(d[1]), "+f"(d[2]), "+f"(d[3])
        : "r"(a[0]), "r"(a[1]), "r"(a[2]), "r"(a[3]), "r"(b[0]), "r"(b[1]));
}

// ---------------- prepass kernels ----------------
__global__ void prep_x(const float* __restrict__ x) {
    size_t i = (size_t)blockIdx.x * 256 + threadIdx.x;   // float4 index
    if (i * 4 >= XN) return;
    float4 v = __ldg((const float4*)x + i);
    __nv_bfloat16 h0 = __float2bfloat16(v.x), h1 = __float2bfloat16(v.y);
    __nv_bfloat16 h2 = __float2bfloat16(v.z), h3 = __float2bfloat16(v.w);
    __nv_bfloat16 l0 = __float2bfloat16(v.x - __bfloat162float(h0));
    __nv_bfloat16 l1 = __float2bfloat16(v.y - __bfloat162float(h1));
    __nv_bfloat16 l2 = __float2bfloat16(v.z - __bfloat162float(h2));
    __nv_bfloat16 l3 = __float2bfloat16(v.w - __bfloat162float(h3));
    ((__nv_bfloat162*)g_xh)[i*2]   = __nv_bfloat162(h0, h1);
    ((__nv_bfloat162*)g_xh)[i*2+1] = __nv_bfloat162(h2, h3);
    ((__nv_bfloat162*)g_xl)[i*2]   = __nv_bfloat162(l0, l1);
    ((__nv_bfloat162*)g_xl)[i*2+1] = __nv_bfloat162(l2, l3);
}

__global__ void prep_w(const float* __restrict__ w) {
    int i = blockIdx.x * 256 + threadIdx.x;
    if (i >= WN) return;
    int ci  = i & 63;
    int co  = (i >> 6) & 127;
    int tap = i >> 13;
    int kd = tap / 9, kh = (tap / 3) % 3, kw = tap % 3;
    int ftap = (2-kd)*9 + (2-kh)*3 + (2-kw);
    float v = __ldg(w + (size_t)ftap * CI * CO + ci * CO + co);
    __nv_bfloat16 h = __float2bfloat16(v);
    g_wh[i] = h;
    g_wl[i] = __float2bfloat16(v - __bfloat162float(h));
}

__global__ void zero_stats_kernel() {
    int t = threadIdx.x;
    if (t < B_*NGRP) { g_sum[t] = 0.f; g_ssq[t] = 0.f; }
}

// ---------------- main conv kernel: mma.sync implicit GEMM -------------------
// CTA = 128 raster positions x 128 c_out, 8 warps; warp tile 32(M) x 64(N).
__global__ void __launch_bounds__(256, 2)
conv_mma_kernel()
{
    extern __shared__ __align__(16) uint16_t sm[];
    uint16_t* sAH = sm;
    uint16_t* sAL = sm + TILE_E;
    uint16_t* sBH = sm + 2*TILE_E;
    uint16_t* sBL = sm + 3*TILE_E;
    __shared__ float red[32];   // [0:16) sums [slot][g], [16:32) ssq [slot][g]

    const int tid  = threadIdx.x;
    const int lane = tid & 31;
    const int wrp  = tid >> 5;
    const int mw   = wrp & 3;       // M block: mw*32
    const int nw   = wrp >> 2;      // N block: nw*64
    const int gid  = lane >> 2;     // fragment group row/col
    const int tig  = lane & 3;

    if (tid < 32) red[tid] = 0.f;

    const int tile = blockIdx.x;
    // staging role: each thread owns (row = tid>>1, half = tid&1)
    const int srow  = tid >> 1;
    const int shalf = tid & 1;
    const int spos  = tile * MTILE + srow;
    const int sb    = spos / VOL;
    const int swv   = spos % VOL;
    const int sd = swv / (DO*DO);
    const int sh = (swv / DO) % DO;
    const int sw = swv % DO;
    const size_t sbase = (size_t)sb * (DI*DI*DI);
    uint16_t* aDstH = sAH + srow*STR + shalf*32;
    uint16_t* aDstL = sAL + srow*STR + shalf*32;
    uint16_t* bDstH = sBH + srow*STR + shalf*32;
    uint16_t* bDstL = sBL + srow*STR + shalf*32;

    float acc[2][8][4];
    #pragma unroll
    for (int m = 0; m < 2; ++m)
        #pragma unroll
        for (int n = 0; n < 8; ++n)
            #pragma unroll
            for (int k = 0; k < 4; ++k) acc[m][n][k] = 0.f;

    for (int tap = 0; tap < 27; ++tap) {
        const int kd = tap / 9, kh = (tap / 3) % 3, kw = tap % 3;

        __syncthreads();   // previous tap's compute done before overwrite

        // ---- stage A: x rows (hi+lo), zero-padded out of bounds ----
        {
            const int id = sd + kd - 2, ih = sh + kh - 2, iw = sw + kw - 2;
            const bool ok = (unsigned)id < DI && (unsigned)ih < DI && (unsigned)iw < DI;
            if (ok) {
                const size_t eoff = (sbase + (size_t)((id*DI + ih)*DI + iw)) * CI + shalf*32;
                const uint4* ph = (const uint4*)(g_xh + eoff);
                const uint4* pl = (const uint4*)(g_xl + eoff);
                #pragma unroll
                for (int j = 0; j < 4; ++j) ((uint4*)aDstH)[j] = __ldg(ph + j);
                #pragma unroll
                for (int j = 0; j < 4; ++j) ((uint4*)aDstL)[j] = __ldg(pl + j);
            } else {
                uint4 z = make_uint4(0,0,0,0);
                #pragma unroll
                for (int j = 0; j < 4; ++j) ((uint4*)aDstH)[j] = z;
                #pragma unroll
                for (int j = 0; j < 4; ++j) ((uint4*)aDstL)[j] = z;
            }
        }
        // ---- stage B: weight slice [co][ci] hi+lo ----
        {
            const size_t woff = (size_t)tap * CI * CO + srow*CI + shalf*32;
            const uint4* ph = (const uint4*)(g_wh + woff);
            const uint4* pl = (const uint4*)(g_wl + woff);
            #pragma unroll
            for (int j = 0; j < 4; ++j) ((uint4*)bDstH)[j] = __ldg(ph + j);
            #pragma unroll
            for (int j = 0; j < 4; ++j) ((uint4*)bDstL)[j] = __ldg(pl + j);
        }
        __syncthreads();

        // ---- compute: 4 K-steps x (hi*hi + lo*hi + hi*lo) ----
        #pragma unroll
        for (int ks = 0; ks < 4; ++ks) {
            const int k0 = ks * 16;
            uint32_t ah[2][4], bh[8][2];
            #pragma unroll
            for (int m = 0; m < 2; ++m) {
                const int r = mw*32 + m*16 + gid;
                const uint16_t* p = sAH + r*STR + k0 + 2*tig;
                ah[m][0] = *(const uint32_t*)(p);
                ah[m][1] = *(const uint32_t*)(p + 8*STR);
                ah[m][2] = *(const uint32_t*)(p + 8);
                ah[m][3] = *(const uint32_t*)(p + 8*STR + 8);
            }
            #pragma unroll
            for (int n = 0; n < 8; ++n) {
                const int c = nw*64 + n*8 + gid;
                const uint16_t* p = sBH + c*STR + k0 + 2*tig;
                bh[n][0] = *(const uint32_t*)(p);
                bh[n][1] = *(const uint32_t*)(p + 8);
            }
            #pragma unroll
            for (int m = 0; m < 2; ++m)
                #pragma unroll
                for (int n = 0; n < 8; ++n)
                    mma16816(acc[m][n], ah[m], bh[n]);   // hi*hi

            uint32_t al[2][4];
            #pragma unroll
            for (int m = 0; m < 2; ++m) {
                const int r = mw*32 + m*16 + gid;
                const uint16_t* p = sAL + r*STR + k0 + 2*tig;
                al[m][0] = *(const uint32_t*)(p);
                al[m][1] = *(const uint32_t*)(p + 8*STR);
                al[m][2] = *(const uint32_t*)(p + 8);
                al[m][3] = *(const uint32_t*)(p + 8*STR + 8);
            }
            #pragma unroll
            for (int m = 0; m < 2; ++m)
                #pragma unroll
                for (int n = 0; n < 8; ++n)
                    mma16816(acc[m][n], al[m], bh[n]);   // lo*hi

            #pragma unroll
            for (int n = 0; n < 8; ++n) {               // overwrite bh with B-lo
                const int c = nw*64 + n*8 + gid;
                const uint16_t* p = sBL + c*STR + k0 + 2*tig;
                bh[n][0] = *(const uint32_t*)(p);
                bh[n][1] = *(const uint32_t*)(p + 8);
            }
            #pragma unroll
            for (int m = 0; m < 2; ++m)
                #pragma unroll
                for (int n = 0; n < 8; ++n)
                    mma16816(acc[m][n], ah[m], bh[n]);   // hi*lo
        }
    }

    // ---- epilogue: ReLU, store, GroupNorm partial stats ----
    const int b0 = (tile * MTILE) / VOL;
    #pragma unroll
    for (int m = 0; m < 2; ++m) {
        #pragma unroll
        for (int rh = 0; rh < 2; ++rh) {
            const int rr  = mw*32 + m*16 + gid + rh*8;
            const int pos = tile * MTILE + rr;
            const int slot = pos / VOL - b0;
            float* dst = g_y + (size_t)pos * CO + nw*64 + 2*tig;
            float s[4] = {0.f,0.f,0.f,0.f}, q[4] = {0.f,0.f,0.f,0.f};
            #pragma unroll
            for (int n = 0; n < 8; ++n) {
                float v0 = fmaxf(acc[m][n][rh*2 + 0], 0.f);
                float v1 = fmaxf(acc[m][n][rh*2 + 1], 0.f);
                *(float2*)(dst + n*8) = make_float2(v0, v1);
                s[n>>1] += v0 + v1;
                q[n>>1] += v0*v0 + v1*v1;
            }
            #pragma unroll
            for (int g = 0; g < 4; ++g) {
                atomicAdd(&red[slot*8 + nw*4 + g],      s[g]);
                atomicAdd(&red[16 + slot*8 + nw*4 + g], q[g]);
            }
        }
    }
    __syncthreads();

    if (tid < 32) {
        const int isq = tid >> 4;        // 0: sum, 1: ssq
        const int sl  = (tid >> 3) & 1;
        const int g   = tid & 7;
        const int bb  = b0 + sl;
        if (bb < B_) {
            float v = red[tid];
            if (!isq) atomicAdd(&g_sum[bb*NGRP + g], v);
            else      atomicAdd(&g_ssq[bb*NGRP + g], v);
        }
    }
}

// ---------------- normalize ----------------
__global__ void norm_kernel(const float* __restrict__ gn_scale,
                            const float* __restrict__ gn_bias,
                            float* __restrict__ out)
{
    const int i = blockIdx.x * blockDim.x + threadIdx.x;   // float4 index
    const size_t e = (size_t)i * 4;
    if (e >= Y_ELEMS) return;
    const int c    = (int)(e & (CO-1));
    const int rest = (int)(e >> 7);
    const int b    = rest / VOL;
    const int g    = c >> 4;
    const float cnt = (float)(VOL * (CO/NGRP));
    const float m   = g_sum[b*NGRP + g] / cnt;
    const float var = g_ssq[b*NGRP + g] / cnt - m*m;
    const float inv = rsqrtf(var + EPS);
    const float4 v  = *(const float4*)(g_y + e);
    const float4 sc = __ldg((const float4*)(gn_scale + c));
    const float4 bi = __ldg((const float4*)(gn_bias + c));
    float4 o;
    o.x = (v.x - m) * inv * sc.x + bi.x;
    o.y = (v.y - m) * inv * sc.y + bi.y;
    o.z = (v.z - m) * inv * sc.z + bi.z;
    o.w = (v.w - m) * inv * sc.w + bi.w;
    *(float4*)(out + e) = o;
}

extern "C" void kernel_launch(void* const* d_in, const int* in_sizes, int n_in,
                              void* d_out, int out_size)
{
    const float* x  = (const float*)d_in[0];
    const float* w  = (const float*)d_in[1];
    const float* sc = (const float*)d_in[2];
    const float* bi = (const float*)d_in[3];
    float* out = (float*)d_out;

    cudaFuncSetAttribute(conv_mma_kernel,
                         cudaFuncAttributeMaxDynamicSharedMemorySize, DYN_SMEM);

    prep_x<<<(unsigned)((XN/4 + 255) / 256), 256>>>(x);
    prep_w<<<(WN + 255) / 256, 256>>>(w);
    zero_stats_kernel<<<1, 128>>>();
    conv_mma_kernel<<<NTILES, 256, DYN_SMEM>>>();

    const int total4 = (int)(Y_ELEMS / 4);
    norm_kernel<<<(total4 + 255) / 256, 256>>>(sc, bi, out);
}